// round 1
// baseline (speedup 1.0000x reference)
#include <cuda_runtime.h>
#include <cuda_bf16.h>

// ---------------------------------------------------------------------------
// Problem constants
// ---------------------------------------------------------------------------
#define CC     256          // channels
#define NTOK   4096         // H*W
#define BB     2            // batch
#define BN     (BB*NTOK)    // 8192 tokens
#define RED    64
#define NH     4
#define HD     16
#define QKV_O  192          // 3*RED
#define OPROJ  320          // 192 qkv + 128 conv1
#define LN_EPS 1e-5f
#define ATT_SCALE 0.25f     // HD^-0.5

// ---------------------------------------------------------------------------
// Device scratch (no allocations allowed)
// ---------------------------------------------------------------------------
__device__ float g_wcomb[OPROJ * CC];     // rows 0..191: qkv_w*norm_w ; 192..319: conv1_w
__device__ float g_Sq[QKV_O];             // sum_c norm_w[c]*qkv_w[o,c]
__device__ float g_Sb[QKV_O];             // sum_c norm_b[c]*qkv_w[o,c]
__device__ float g_mu[BN];
__device__ float g_rsig[BN];
__device__ float g_q[BB * NH * NTOK * HD];
__device__ float g_k[BB * NH * NTOK * HD];
__device__ float g_v[BB * NH * NTOK * HD];
__device__ float g_dynpart[2 * BN];       // two deterministic partial sums of conv2
__device__ float g_ao[BN * RED];          // attention output, [tok][r=h*16+d]

// ---------------------------------------------------------------------------
// packed f32x2 helpers (PTX-only on Blackwell; doubles fma-pipe throughput)
// ---------------------------------------------------------------------------
union F2U { float2 f; unsigned long long u; };

__device__ __forceinline__ float2 ffma2(float2 a, float2 b, float2 c) {
    F2U ua, ub, uc, ud;
    ua.f = a; ub.f = b; uc.f = c;
    asm("fma.rn.f32x2 %0, %1, %2, %3;" : "=l"(ud.u) : "l"(ua.u), "l"(ub.u), "l"(uc.u));
    return ud.f;
}
__device__ __forceinline__ float2 fmul2(float2 a, float2 b) {
    F2U ua, ub, ud;
    ua.f = a; ub.f = b;
    asm("mul.rn.f32x2 %0, %1, %2;" : "=l"(ud.u) : "l"(ua.u), "l"(ub.u));
    return ud.f;
}

// ---------------------------------------------------------------------------
// Kernel 0: fold norm_w into qkv weights, build combined [320,256] weight,
// and the per-output LN correction sums Sq, Sb.
// ---------------------------------------------------------------------------
__global__ __launch_bounds__(256) void prep_kernel(const float* __restrict__ qkv_w,
                                                   const float* __restrict__ conv1_w,
                                                   const float* __restrict__ norm_w,
                                                   const float* __restrict__ norm_b) {
    int o = blockIdx.x;
    int c = threadIdx.x;
    __shared__ float r1[256];
    __shared__ float r2[256];
    float wc;
    if (o < QKV_O) {
        float qw = qkv_w[o * CC + c];
        wc = qw * norm_w[c];
        r1[c] = wc;                 // contribution to Sq
        r2[c] = qw * norm_b[c];     // contribution to Sb
    } else {
        wc = conv1_w[(o - QKV_O) * CC + c];
        r1[c] = 0.f;
        r2[c] = 0.f;
    }
    g_wcomb[o * CC + c] = wc;
    __syncthreads();
    for (int s = 128; s > 0; s >>= 1) {
        if (c < s) { r1[c] += r1[c + s]; r2[c] += r2[c + s]; }
        __syncthreads();
    }
    if (c == 0 && o < QKV_O) { g_Sq[o] = r1[0]; g_Sb[o] = r2[0]; }
}

// ---------------------------------------------------------------------------
// Kernel 1: per-token LayerNorm stats over the channel dim.
// x layout: [b][c][n], token reads are coalesced across threads.
// ---------------------------------------------------------------------------
__global__ __launch_bounds__(128) void stats_kernel(const float* __restrict__ x) {
    int tok = blockIdx.x * 128 + threadIdx.x;
    int b = tok >> 12;
    int n = tok & (NTOK - 1);
    const float* xp = x + (size_t)b * CC * NTOK + n;
    float s = 0.f, ss = 0.f;
#pragma unroll 8
    for (int c = 0; c < CC; c++) {
        float v = xp[(size_t)c * NTOK];
        s += v;
        ss += v * v;
    }
    float mu = s * (1.f / CC);
    float var = ss * (1.f / CC) - mu * mu;
    g_mu[tok] = mu;
    g_rsig[tok] = rsqrtf(var + LN_EPS);
}

// ---------------------------------------------------------------------------
// Kernel 2: projection GEMM  G[o, tok] = sum_c wcomb[o,c] * x[b,c,n]
//   oT 0..2  -> q/k/v with LN affine epilogue -> g_q/g_k/g_v ([bh][n][d])
//   oT 3..4  -> conv1 + relu + conv2 partial sums -> g_dynpart
// Block: 64 outputs x 128 tokens, 256 threads, 4x8 register tile.
// ---------------------------------------------------------------------------
__global__ __launch_bounds__(256) void proj_kernel(const float* __restrict__ x,
                                                   const float* __restrict__ conv1_b,
                                                   const float* __restrict__ conv2_w) {
    extern __shared__ float sm[];
    float* ws = sm;               // 64 x 256
    float* xs = sm + 64 * 256;    // 64 x 128 (k-chunk x tokens)

    int tid = threadIdx.x;
    int oT = blockIdx.y;
    int tokb = blockIdx.x * 128;
    int b = tokb >> 12;
    int nb = tokb & (NTOK - 1);

    // stage the 64x256 weight slice once
    for (int i = tid; i < 64 * 256; i += 256)
        ws[i] = g_wcomb[oT * 64 * 256 + i];

    int tx = tid & 15;    // token group  (8 tokens)
    int ty = tid >> 4;    // output group (4 outputs)

    float acc[4][8];
#pragma unroll
    for (int i = 0; i < 4; i++)
#pragma unroll
        for (int j = 0; j < 8; j++) acc[i][j] = 0.f;

    for (int kc = 0; kc < 4; kc++) {
        __syncthreads();
        for (int i = tid; i < 64 * 128; i += 256) {
            int kk = i >> 7;
            int t = i & 127;
            xs[i] = x[((size_t)b * CC + kc * 64 + kk) * NTOK + nb + t];
        }
        __syncthreads();
#pragma unroll 2
        for (int kk = 0; kk < 64; kk++) {
            int c = kc * 64 + kk;
            float a0 = ws[(ty * 4 + 0) * 256 + c];
            float a1 = ws[(ty * 4 + 1) * 256 + c];
            float a2 = ws[(ty * 4 + 2) * 256 + c];
            float a3 = ws[(ty * 4 + 3) * 256 + c];
            const float* xr = &xs[kk * 128 + tx * 8];
            float4 b0 = *(const float4*)xr;
            float4 b1 = *(const float4*)(xr + 4);
            acc[0][0] += a0 * b0.x; acc[0][1] += a0 * b0.y; acc[0][2] += a0 * b0.z; acc[0][3] += a0 * b0.w;
            acc[0][4] += a0 * b1.x; acc[0][5] += a0 * b1.y; acc[0][6] += a0 * b1.z; acc[0][7] += a0 * b1.w;
            acc[1][0] += a1 * b0.x; acc[1][1] += a1 * b0.y; acc[1][2] += a1 * b0.z; acc[1][3] += a1 * b0.w;
            acc[1][4] += a1 * b1.x; acc[1][5] += a1 * b1.y; acc[1][6] += a1 * b1.z; acc[1][7] += a1 * b1.w;
            acc[2][0] += a2 * b0.x; acc[2][1] += a2 * b0.y; acc[2][2] += a2 * b0.z; acc[2][3] += a2 * b0.w;
            acc[2][4] += a2 * b1.x; acc[2][5] += a2 * b1.y; acc[2][6] += a2 * b1.z; acc[2][7] += a2 * b1.w;
            acc[3][0] += a3 * b0.x; acc[3][1] += a3 * b0.y; acc[3][2] += a3 * b0.z; acc[3][3] += a3 * b0.w;
            acc[3][4] += a3 * b1.x; acc[3][5] += a3 * b1.y; acc[3][6] += a3 * b1.z; acc[3][7] += a3 * b1.w;
        }
    }

    if (oT < 3) {
        float muv[8], rsv[8];
#pragma unroll
        for (int j = 0; j < 8; j++) {
            int tok = tokb + tx * 8 + j;
            muv[j] = g_mu[tok];
            rsv[j] = g_rsig[tok];
        }
#pragma unroll
        for (int i = 0; i < 4; i++) {
            int o = oT * 64 + ty * 4 + i;
            float sq = g_Sq[o];
            float sb = g_Sb[o];
            int which = o >> 6;          // 0=q 1=k 2=v
            int oo = o & 63;
            int h = oo >> 4;
            int d = oo & 15;
            float* dst = (which == 0) ? g_q : (which == 1) ? g_k : g_v;
#pragma unroll
            for (int j = 0; j < 8; j++) {
                int n = nb + tx * 8 + j;
                float val = rsv[j] * (acc[i][j] - muv[j] * sq) + sb;
                dst[(((size_t)b * NH + h) * NTOK + n) * HD + d] = val;
            }
        }
    } else {
        // conv path: d1 = relu(acc + conv1_b), partial dyn = sum conv2_w * d1
        float part[8];
#pragma unroll
        for (int j = 0; j < 8; j++) part[j] = 0.f;
#pragma unroll
        for (int i = 0; i < 4; i++) {
            int jc = oT * 64 + ty * 4 + i - QKV_O;
            float cb = conv1_b[jc];
            float cw = conv2_w[jc];
#pragma unroll
            for (int j = 0; j < 8; j++) {
                float d1 = fmaxf(acc[i][j] + cb, 0.f);
                part[j] += cw * d1;
            }
        }
        __syncthreads();              // xs reuse as reduction buffer
        float* red = xs;              // 16 x 128
#pragma unroll
        for (int j = 0; j < 8; j++) red[ty * 128 + tx * 8 + j] = part[j];
        __syncthreads();
        if (tid < 128) {
            float s = 0.f;
#pragma unroll
            for (int yy = 0; yy < 16; yy++) s += red[yy * 128 + tid];
            g_dynpart[(oT - 3) * BN + tokb + tid] = s;
        }
    }
}

// ---------------------------------------------------------------------------
// Kernel 3: attention. One thread = one query. K/V tiled through smem,
// key vector reads are warp-broadcast (conflict-free). Online softmax with
// the cheap p=1 path; all dots/accums in packed f32x2.
// Epilogue folds the per-query dyn scaling and 1/l.
// ---------------------------------------------------------------------------
__global__ __launch_bounds__(256) void attn_kernel(const float* __restrict__ conv2_b) {
    __shared__ float ks[256 * HD];
    __shared__ float vs[256 * HD];

    int bh = blockIdx.y;                        // b*4 + h
    int tid = threadIdx.x;
    int n = blockIdx.x * 256 + tid;

    const float* qp = g_q + ((size_t)bh * NTOK + n) * HD;
    float2 q2[8];
#pragma unroll
    for (int i = 0; i < 4; i++) {
        float4 t = *(const float4*)(qp + i * 4);
        q2[2 * i]     = make_float2(t.x, t.y);
        q2[2 * i + 1] = make_float2(t.z, t.w);
    }

    float m = -1e30f;
    float l = 0.f;
    float2 o2[8];
#pragma unroll
    for (int i = 0; i < 8; i++) o2[i] = make_float2(0.f, 0.f);

    for (int kt = 0; kt < NTOK / 256; kt++) {
        __syncthreads();
        const float4* kg = (const float4*)(g_k + ((size_t)bh * NTOK + kt * 256) * HD);
        const float4* vg = (const float4*)(g_v + ((size_t)bh * NTOK + kt * 256) * HD);
#pragma unroll
        for (int i = tid; i < 256 * HD / 4; i += 256) {
            ((float4*)ks)[i] = kg[i];
            ((float4*)vs)[i] = vg[i];
        }
        __syncthreads();

#pragma unroll 2
        for (int mm = 0; mm < 256; mm++) {
            const float4* kp = (const float4*)&ks[mm * HD];
            float4 k0 = kp[0], k1 = kp[1], k2 = kp[2], k3 = kp[3];
            float2 acc = fmul2(q2[0], make_float2(k0.x, k0.y));
            acc = ffma2(q2[1], make_float2(k0.z, k0.w), acc);
            acc = ffma2(q2[2], make_float2(k1.x, k1.y), acc);
            acc = ffma2(q2[3], make_float2(k1.z, k1.w), acc);
            acc = ffma2(q2[4], make_float2(k2.x, k2.y), acc);
            acc = ffma2(q2[5], make_float2(k2.z, k2.w), acc);
            acc = ffma2(q2[6], make_float2(k3.x, k3.y), acc);
            acc = ffma2(q2[7], make_float2(k3.z, k3.w), acc);
            float s = (acc.x + acc.y) * ATT_SCALE;

            const float4* vp = (const float4*)&vs[mm * HD];
            float4 va = vp[0], vb = vp[1], vc = vp[2], vd = vp[3];
            if (s > m) {
                float corr = __expf(m - s);
                m = s;
                l = l * corr + 1.f;
                float2 cc = make_float2(corr, corr);
                o2[0] = ffma2(cc, o2[0], make_float2(va.x, va.y));
                o2[1] = ffma2(cc, o2[1], make_float2(va.z, va.w));
                o2[2] = ffma2(cc, o2[2], make_float2(vb.x, vb.y));
                o2[3] = ffma2(cc, o2[3], make_float2(vb.z, vb.w));
                o2[4] = ffma2(cc, o2[4], make_float2(vc.x, vc.y));
                o2[5] = ffma2(cc, o2[5], make_float2(vc.z, vc.w));
                o2[6] = ffma2(cc, o2[6], make_float2(vd.x, vd.y));
                o2[7] = ffma2(cc, o2[7], make_float2(vd.z, vd.w));
            } else {
                float p = __expf(s - m);
                l += p;
                float2 pp = make_float2(p, p);
                o2[0] = ffma2(pp, make_float2(va.x, va.y), o2[0]);
                o2[1] = ffma2(pp, make_float2(va.z, va.w), o2[1]);
                o2[2] = ffma2(pp, make_float2(vb.x, vb.y), o2[2]);
                o2[3] = ffma2(pp, make_float2(vb.z, vb.w), o2[3]);
                o2[4] = ffma2(pp, make_float2(vc.x, vc.y), o2[4]);
                o2[5] = ffma2(pp, make_float2(vc.z, vc.w), o2[5]);
                o2[6] = ffma2(pp, make_float2(vd.x, vd.y), o2[6]);
                o2[7] = ffma2(pp, make_float2(vd.z, vd.w), o2[7]);
            }
        }
    }

    int b = bh >> 2;
    int h = bh & 3;
    int tok = b * NTOK + n;
    float dyn = g_dynpart[tok] + g_dynpart[BN + tok] + conv2_b[0];
    float sc = dyn / l;
    float* dst = g_ao + (size_t)tok * RED + h * HD;
#pragma unroll
    for (int i = 0; i < 4; i++) {
        float4 t = make_float4(o2[2 * i].x * sc, o2[2 * i].y * sc,
                               o2[2 * i + 1].x * sc, o2[2 * i + 1].y * sc);
        *(float4*)(dst + i * 4) = t;
    }
}

// ---------------------------------------------------------------------------
// Kernel 4: out-projection + residual + sigmoid.
// Block: 64 channels x 64 tokens, smem tiles transposed for conflict-free reads.
// ---------------------------------------------------------------------------
__global__ __launch_bounds__(256) void out_kernel(const float* __restrict__ x,
                                                  const float* __restrict__ out_w,
                                                  const float* __restrict__ gamma,
                                                  float* __restrict__ out) {
    __shared__ float wsl[64 * 64];   // [r][c]
    __shared__ float aos[64 * 64];   // [r][t]
    int tid = threadIdx.x;
    int tokb = blockIdx.x * 64;
    int cT = blockIdx.y;
    int b = tokb >> 12;
    int nb = tokb & (NTOK - 1);

    for (int i = tid; i < 64 * 64; i += 256) {
        int t = i >> 6;
        int r = i & 63;
        aos[r * 64 + t] = g_ao[(size_t)(tokb + t) * RED + r];
        wsl[r * 64 + t] = out_w[(size_t)(cT * 64 + t) * RED + r];  // t as c-index here
    }
    __syncthreads();

    int tx = tid & 15;   // token group (4 tokens)
    int ty = tid >> 4;   // channel group (4 channels)
    float acc[4][4];
#pragma unroll
    for (int i = 0; i < 4; i++)
#pragma unroll
        for (int j = 0; j < 4; j++) acc[i][j] = 0.f;

#pragma unroll 4
    for (int r = 0; r < 64; r++) {
        float a0 = wsl[r * 64 + ty * 4 + 0];
        float a1 = wsl[r * 64 + ty * 4 + 1];
        float a2 = wsl[r * 64 + ty * 4 + 2];
        float a3 = wsl[r * 64 + ty * 4 + 3];
        float4 bv = *(const float4*)&aos[r * 64 + tx * 4];
        acc[0][0] += a0 * bv.x; acc[0][1] += a0 * bv.y; acc[0][2] += a0 * bv.z; acc[0][3] += a0 * bv.w;
        acc[1][0] += a1 * bv.x; acc[1][1] += a1 * bv.y; acc[1][2] += a1 * bv.z; acc[1][3] += a1 * bv.w;
        acc[2][0] += a2 * bv.x; acc[2][1] += a2 * bv.y; acc[2][2] += a2 * bv.z; acc[2][3] += a2 * bv.w;
        acc[3][0] += a3 * bv.x; acc[3][1] += a3 * bv.y; acc[3][2] += a3 * bv.z; acc[3][3] += a3 * bv.w;
    }

    float g = gamma[0];
#pragma unroll
    for (int i = 0; i < 4; i++) {
        int c = cT * 64 + ty * 4 + i;
        size_t base = ((size_t)b * CC + c) * NTOK + nb + tx * 4;
        float4 xv = *(const float4*)(x + base);
        float4 r;
        float z0 = g * acc[i][0] + xv.x;
        float z1 = g * acc[i][1] + xv.y;
        float z2 = g * acc[i][2] + xv.z;
        float z3 = g * acc[i][3] + xv.w;
        r.x = 1.f / (1.f + __expf(-z0));
        r.y = 1.f / (1.f + __expf(-z1));
        r.z = 1.f / (1.f + __expf(-z2));
        r.w = 1.f / (1.f + __expf(-z3));
        *(float4*)(out + base) = r;
    }
}

// ---------------------------------------------------------------------------
// Launch
// ---------------------------------------------------------------------------
extern "C" void kernel_launch(void* const* d_in, const int* in_sizes, int n_in,
                              void* d_out, int out_size) {
    const float* x       = (const float*)d_in[0];
    const float* norm_w  = (const float*)d_in[1];
    const float* norm_b  = (const float*)d_in[2];
    const float* qkv_w   = (const float*)d_in[3];
    const float* out_w   = (const float*)d_in[4];
    const float* conv1_w = (const float*)d_in[5];
    const float* conv1_b = (const float*)d_in[6];
    const float* conv2_w = (const float*)d_in[7];
    const float* conv2_b = (const float*)d_in[8];
    const float* gamma   = (const float*)d_in[9];
    float* out = (float*)d_out;
    (void)in_sizes; (void)n_in; (void)out_size;

    const int proj_smem = (64 * 256 + 64 * 128) * sizeof(float);   // 98304
    cudaFuncSetAttribute(proj_kernel, cudaFuncAttributeMaxDynamicSharedMemorySize, proj_smem);

    prep_kernel<<<OPROJ, 256>>>(qkv_w, conv1_w, norm_w, norm_b);
    stats_kernel<<<BN / 128, 128>>>(x);
    proj_kernel<<<dim3(BN / 128, 5), 256, proj_smem>>>(x, conv1_b, conv2_w);
    attn_kernel<<<dim3(NTOK / 256, BB * NH), 256>>>(conv2_b);
    out_kernel<<<dim3(BN / 64, CC / 64), 256>>>(x, out_w, gamma, out);
}

// round 2
// speedup vs baseline: 1.4023x; 1.4023x over previous
#include <cuda_runtime.h>
#include <cuda_bf16.h>

// ---------------------------------------------------------------------------
// Problem constants
// ---------------------------------------------------------------------------
#define CC     256          // channels
#define NTOK   4096         // H*W
#define BB     2            // batch
#define BN     (BB*NTOK)    // 8192 tokens
#define RED    64
#define NH     4
#define HD     16
#define QKV_O  192          // 3*RED
#define OPROJ  320          // 192 qkv + 128 conv1
#define LN_EPS 1e-5f
#define ATT_SCALE 0.25f     // HD^-0.5
#define NSPLIT 4            // KV splits for occupancy
#define KPS    (NTOK/NSPLIT)  // keys per split = 1024

// ---------------------------------------------------------------------------
// Device scratch (no allocations allowed)
// ---------------------------------------------------------------------------
__device__ float g_wcomb[OPROJ * CC];     // rows 0..191: qkv_w*norm_w ; 192..319: conv1_w
__device__ float g_Sq[QKV_O];             // sum_c norm_w[c]*qkv_w[o,c]
__device__ float g_Sb[QKV_O];             // sum_c norm_b[c]*qkv_w[o,c]
__device__ float g_mu[BN];
__device__ float g_rsig[BN];
__device__ float g_q[BB * NH * NTOK * HD];
__device__ float g_k[BB * NH * NTOK * HD];
__device__ float g_v[BB * NH * NTOK * HD];
__device__ float g_dynpart[2 * BN];       // two deterministic partial sums of conv2
__device__ float g_ao[BN * RED];          // attention output, [tok][r=h*16+d]

// split-KV partials
__device__ float g_pm[BB * NH * NSPLIT * NTOK];          // [bh][s][n]
__device__ float g_pl[BB * NH * NSPLIT * NTOK];
__device__ float g_po[BB * NH * NSPLIT * HD * NTOK];     // [bh][s][d][n]

// ---------------------------------------------------------------------------
// packed f32x2 helpers (PTX-only on Blackwell; doubles fma-pipe throughput)
// ---------------------------------------------------------------------------
union F2U { float2 f; unsigned long long u; };

__device__ __forceinline__ float2 ffma2(float2 a, float2 b, float2 c) {
    F2U ua, ub, uc, ud;
    ua.f = a; ub.f = b; uc.f = c;
    asm("fma.rn.f32x2 %0, %1, %2, %3;" : "=l"(ud.u) : "l"(ua.u), "l"(ub.u), "l"(uc.u));
    return ud.f;
}
__device__ __forceinline__ float2 fmul2(float2 a, float2 b) {
    F2U ua, ub, ud;
    ua.f = a; ub.f = b;
    asm("mul.rn.f32x2 %0, %1, %2;" : "=l"(ud.u) : "l"(ua.u), "l"(ub.u));
    return ud.f;
}

// ---------------------------------------------------------------------------
// Kernel 0: fold norm_w into qkv weights, build combined [320,256] weight,
// and the per-output LN correction sums Sq, Sb.
// ---------------------------------------------------------------------------
__global__ __launch_bounds__(256) void prep_kernel(const float* __restrict__ qkv_w,
                                                   const float* __restrict__ conv1_w,
                                                   const float* __restrict__ norm_w,
                                                   const float* __restrict__ norm_b) {
    int o = blockIdx.x;
    int c = threadIdx.x;
    __shared__ float r1[256];
    __shared__ float r2[256];
    float wc;
    if (o < QKV_O) {
        float qw = qkv_w[o * CC + c];
        wc = qw * norm_w[c];
        r1[c] = wc;                 // contribution to Sq
        r2[c] = qw * norm_b[c];     // contribution to Sb
    } else {
        wc = conv1_w[(o - QKV_O) * CC + c];
        r1[c] = 0.f;
        r2[c] = 0.f;
    }
    g_wcomb[o * CC + c] = wc;
    __syncthreads();
    for (int s = 128; s > 0; s >>= 1) {
        if (c < s) { r1[c] += r1[c + s]; r2[c] += r2[c + s]; }
        __syncthreads();
    }
    if (c == 0 && o < QKV_O) { g_Sq[o] = r1[0]; g_Sb[o] = r2[0]; }
}

// ---------------------------------------------------------------------------
// Kernel 1: per-token LayerNorm stats over the channel dim.
// ---------------------------------------------------------------------------
__global__ __launch_bounds__(128) void stats_kernel(const float* __restrict__ x) {
    int tok = blockIdx.x * 128 + threadIdx.x;
    int b = tok >> 12;
    int n = tok & (NTOK - 1);
    const float* xp = x + (size_t)b * CC * NTOK + n;
    float s = 0.f, ss = 0.f;
#pragma unroll 8
    for (int c = 0; c < CC; c++) {
        float v = xp[(size_t)c * NTOK];
        s += v;
        ss += v * v;
    }
    float mu = s * (1.f / CC);
    float var = ss * (1.f / CC) - mu * mu;
    g_mu[tok] = mu;
    g_rsig[tok] = rsqrtf(var + LN_EPS);
}

// ---------------------------------------------------------------------------
// Kernel 2: projection GEMM  G[o, tok] = sum_c wcomb[o,c] * x[b,c,n]
// ---------------------------------------------------------------------------
__global__ __launch_bounds__(256) void proj_kernel(const float* __restrict__ x,
                                                   const float* __restrict__ conv1_b,
                                                   const float* __restrict__ conv2_w) {
    extern __shared__ float sm[];
    float* ws = sm;               // 64 x 256
    float* xs = sm + 64 * 256;    // 64 x 128 (k-chunk x tokens)

    int tid = threadIdx.x;
    int oT = blockIdx.y;
    int tokb = blockIdx.x * 128;
    int b = tokb >> 12;
    int nb = tokb & (NTOK - 1);

    for (int i = tid; i < 64 * 256; i += 256)
        ws[i] = g_wcomb[oT * 64 * 256 + i];

    int tx = tid & 15;    // token group  (8 tokens)
    int ty = tid >> 4;    // output group (4 outputs)

    float acc[4][8];
#pragma unroll
    for (int i = 0; i < 4; i++)
#pragma unroll
        for (int j = 0; j < 8; j++) acc[i][j] = 0.f;

    for (int kc = 0; kc < 4; kc++) {
        __syncthreads();
        for (int i = tid; i < 64 * 128; i += 256) {
            int kk = i >> 7;
            int t = i & 127;
            xs[i] = x[((size_t)b * CC + kc * 64 + kk) * NTOK + nb + t];
        }
        __syncthreads();
#pragma unroll 2
        for (int kk = 0; kk < 64; kk++) {
            int c = kc * 64 + kk;
            float a0 = ws[(ty * 4 + 0) * 256 + c];
            float a1 = ws[(ty * 4 + 1) * 256 + c];
            float a2 = ws[(ty * 4 + 2) * 256 + c];
            float a3 = ws[(ty * 4 + 3) * 256 + c];
            const float* xr = &xs[kk * 128 + tx * 8];
            float4 b0 = *(const float4*)xr;
            float4 b1 = *(const float4*)(xr + 4);
            acc[0][0] += a0 * b0.x; acc[0][1] += a0 * b0.y; acc[0][2] += a0 * b0.z; acc[0][3] += a0 * b0.w;
            acc[0][4] += a0 * b1.x; acc[0][5] += a0 * b1.y; acc[0][6] += a0 * b1.z; acc[0][7] += a0 * b1.w;
            acc[1][0] += a1 * b0.x; acc[1][1] += a1 * b0.y; acc[1][2] += a1 * b0.z; acc[1][3] += a1 * b0.w;
            acc[1][4] += a1 * b1.x; acc[1][5] += a1 * b1.y; acc[1][6] += a1 * b1.z; acc[1][7] += a1 * b1.w;
            acc[2][0] += a2 * b0.x; acc[2][1] += a2 * b0.y; acc[2][2] += a2 * b0.z; acc[2][3] += a2 * b0.w;
            acc[2][4] += a2 * b1.x; acc[2][5] += a2 * b1.y; acc[2][6] += a2 * b1.z; acc[2][7] += a2 * b1.w;
            acc[3][0] += a3 * b0.x; acc[3][1] += a3 * b0.y; acc[3][2] += a3 * b0.z; acc[3][3] += a3 * b0.w;
            acc[3][4] += a3 * b1.x; acc[3][5] += a3 * b1.y; acc[3][6] += a3 * b1.z; acc[3][7] += a3 * b1.w;
        }
    }

    if (oT < 3) {
        float muv[8], rsv[8];
#pragma unroll
        for (int j = 0; j < 8; j++) {
            int tok = tokb + tx * 8 + j;
            muv[j] = g_mu[tok];
            rsv[j] = g_rsig[tok];
        }
#pragma unroll
        for (int i = 0; i < 4; i++) {
            int o = oT * 64 + ty * 4 + i;
            float sq = g_Sq[o];
            float sb = g_Sb[o];
            int which = o >> 6;          // 0=q 1=k 2=v
            int oo = o & 63;
            int h = oo >> 4;
            int d = oo & 15;
            float* dst = (which == 0) ? g_q : (which == 1) ? g_k : g_v;
#pragma unroll
            for (int j = 0; j < 8; j++) {
                int n = nb + tx * 8 + j;
                float val = rsv[j] * (acc[i][j] - muv[j] * sq) + sb;
                dst[(((size_t)b * NH + h) * NTOK + n) * HD + d] = val;
            }
        }
    } else {
        float part[8];
#pragma unroll
        for (int j = 0; j < 8; j++) part[j] = 0.f;
#pragma unroll
        for (int i = 0; i < 4; i++) {
            int jc = oT * 64 + ty * 4 + i - QKV_O;
            float cb = conv1_b[jc];
            float cw = conv2_w[jc];
#pragma unroll
            for (int j = 0; j < 8; j++) {
                float d1 = fmaxf(acc[i][j] + cb, 0.f);
                part[j] += cw * d1;
            }
        }
        __syncthreads();
        float* red = xs;              // 16 x 128
#pragma unroll
        for (int j = 0; j < 8; j++) red[ty * 128 + tx * 8 + j] = part[j];
        __syncthreads();
        if (tid < 128) {
            float s = 0.f;
#pragma unroll
            for (int yy = 0; yy < 16; yy++) s += red[yy * 128 + tid];
            g_dynpart[(oT - 3) * BN + tokb + tid] = s;
        }
    }
}

// ---------------------------------------------------------------------------
// Kernel 3: split-KV attention. One thread = one query, one split of keys.
// Grid: (NTOK/256, BB*NH, NSPLIT). Emits per-split (m, l, o[16]) partials.
// ---------------------------------------------------------------------------
__global__ __launch_bounds__(256) void attn_kernel(int dummy) {
    __shared__ float ks[256 * HD];
    __shared__ float vs[256 * HD];

    int bh = blockIdx.y;                        // b*4 + h
    int sp = blockIdx.z;
    int tid = threadIdx.x;
    int n = blockIdx.x * 256 + tid;

    const float* qp = g_q + ((size_t)bh * NTOK + n) * HD;
    float2 q2[8];
#pragma unroll
    for (int i = 0; i < 4; i++) {
        float4 t = *(const float4*)(qp + i * 4);
        q2[2 * i]     = make_float2(t.x, t.y);
        q2[2 * i + 1] = make_float2(t.z, t.w);
    }

    float m = -1e30f;
    float l = 0.f;
    float2 o2[8];
#pragma unroll
    for (int i = 0; i < 8; i++) o2[i] = make_float2(0.f, 0.f);

    for (int kt = 0; kt < KPS / 256; kt++) {
        int kbase = sp * KPS + kt * 256;
        __syncthreads();
        const float4* kg = (const float4*)(g_k + ((size_t)bh * NTOK + kbase) * HD);
        const float4* vg = (const float4*)(g_v + ((size_t)bh * NTOK + kbase) * HD);
#pragma unroll
        for (int i = tid; i < 256 * HD / 4; i += 256) {
            ((float4*)ks)[i] = kg[i];
            ((float4*)vs)[i] = vg[i];
        }
        __syncthreads();

#pragma unroll 2
        for (int mm = 0; mm < 256; mm++) {
            const float4* kp = (const float4*)&ks[mm * HD];
            float4 k0 = kp[0], k1 = kp[1], k2 = kp[2], k3 = kp[3];
            float2 acc = fmul2(q2[0], make_float2(k0.x, k0.y));
            acc = ffma2(q2[1], make_float2(k0.z, k0.w), acc);
            acc = ffma2(q2[2], make_float2(k1.x, k1.y), acc);
            acc = ffma2(q2[3], make_float2(k1.z, k1.w), acc);
            acc = ffma2(q2[4], make_float2(k2.x, k2.y), acc);
            acc = ffma2(q2[5], make_float2(k2.z, k2.w), acc);
            acc = ffma2(q2[6], make_float2(k3.x, k3.y), acc);
            acc = ffma2(q2[7], make_float2(k3.z, k3.w), acc);
            float s = (acc.x + acc.y) * ATT_SCALE;

            const float4* vp = (const float4*)&vs[mm * HD];
            float4 va = vp[0], vb = vp[1], vc = vp[2], vd = vp[3];
            if (s > m) {
                float corr = __expf(m - s);
                m = s;
                l = l * corr + 1.f;
                float2 cc = make_float2(corr, corr);
                o2[0] = ffma2(cc, o2[0], make_float2(va.x, va.y));
                o2[1] = ffma2(cc, o2[1], make_float2(va.z, va.w));
                o2[2] = ffma2(cc, o2[2], make_float2(vb.x, vb.y));
                o2[3] = ffma2(cc, o2[3], make_float2(vb.z, vb.w));
                o2[4] = ffma2(cc, o2[4], make_float2(vc.x, vc.y));
                o2[5] = ffma2(cc, o2[5], make_float2(vc.z, vc.w));
                o2[6] = ffma2(cc, o2[6], make_float2(vd.x, vd.y));
                o2[7] = ffma2(cc, o2[7], make_float2(vd.z, vd.w));
            } else {
                float p = __expf(s - m);
                l += p;
                float2 pp = make_float2(p, p);
                o2[0] = ffma2(pp, make_float2(va.x, va.y), o2[0]);
                o2[1] = ffma2(pp, make_float2(va.z, va.w), o2[1]);
                o2[2] = ffma2(pp, make_float2(vb.x, vb.y), o2[2]);
                o2[3] = ffma2(pp, make_float2(vb.z, vb.w), o2[3]);
                o2[4] = ffma2(pp, make_float2(vc.x, vc.y), o2[4]);
                o2[5] = ffma2(pp, make_float2(vc.z, vc.w), o2[5]);
                o2[6] = ffma2(pp, make_float2(vd.x, vd.y), o2[6]);
                o2[7] = ffma2(pp, make_float2(vd.z, vd.w), o2[7]);
            }
        }
    }

    // write partials: [bh][sp][d][n] layout (coalesced over n)
    size_t pbase = ((size_t)bh * NSPLIT + sp) * NTOK + n;
    g_pm[pbase] = m;
    g_pl[pbase] = l;
    float* po = g_po + ((size_t)bh * NSPLIT + sp) * HD * NTOK + n;
#pragma unroll
    for (int i = 0; i < 8; i++) {
        po[(size_t)(2 * i)     * NTOK] = o2[i].x;
        po[(size_t)(2 * i + 1) * NTOK] = o2[i].y;
    }
}

// ---------------------------------------------------------------------------
// Kernel 3b: combine splits, fold dyn scaling, write g_ao.
// One thread per (bh, n).
// ---------------------------------------------------------------------------
__global__ __launch_bounds__(256) void combine_kernel(const float* __restrict__ conv2_b) {
    int idx = blockIdx.x * 256 + threadIdx.x;     // bh*NTOK + n
    int bh = idx >> 12;
    int n = idx & (NTOK - 1);

    float ms[NSPLIT], ls[NSPLIT];
    float m = -1e30f;
#pragma unroll
    for (int s = 0; s < NSPLIT; s++) {
        size_t p = ((size_t)bh * NSPLIT + s) * NTOK + n;
        ms[s] = g_pm[p];
        ls[s] = g_pl[p];
        m = fmaxf(m, ms[s]);
    }
    float l = 0.f;
    float w[NSPLIT];
#pragma unroll
    for (int s = 0; s < NSPLIT; s++) {
        w[s] = __expf(ms[s] - m);
        l += ls[s] * w[s];
    }

    float o[HD];
#pragma unroll
    for (int d = 0; d < HD; d++) o[d] = 0.f;
#pragma unroll
    for (int s = 0; s < NSPLIT; s++) {
        const float* po = g_po + ((size_t)bh * NSPLIT + s) * HD * NTOK + n;
        float ws = w[s];
#pragma unroll
        for (int d = 0; d < HD; d++)
            o[d] += po[(size_t)d * NTOK] * ws;
    }

    int b = bh >> 2;
    int h = bh & 3;
    int tok = b * NTOK + n;
    float dyn = g_dynpart[tok] + g_dynpart[BN + tok] + conv2_b[0];
    float sc = dyn / l;
    float* dst = g_ao + (size_t)tok * RED + h * HD;
#pragma unroll
    for (int i = 0; i < 4; i++) {
        float4 t = make_float4(o[4 * i] * sc, o[4 * i + 1] * sc,
                               o[4 * i + 2] * sc, o[4 * i + 3] * sc);
        *(float4*)(dst + i * 4) = t;
    }
}

// ---------------------------------------------------------------------------
// Kernel 4: out-projection + residual + sigmoid.
// ---------------------------------------------------------------------------
__global__ __launch_bounds__(256) void out_kernel(const float* __restrict__ x,
                                                  const float* __restrict__ out_w,
                                                  const float* __restrict__ gamma,
                                                  float* __restrict__ out) {
    __shared__ float wsl[64 * 64];   // [r][c]
    __shared__ float aos[64 * 64];   // [r][t]
    int tid = threadIdx.x;
    int tokb = blockIdx.x * 64;
    int cT = blockIdx.y;
    int b = tokb >> 12;
    int nb = tokb & (NTOK - 1);

    for (int i = tid; i < 64 * 64; i += 256) {
        int t = i >> 6;
        int r = i & 63;
        aos[r * 64 + t] = g_ao[(size_t)(tokb + t) * RED + r];
        wsl[r * 64 + t] = out_w[(size_t)(cT * 64 + t) * RED + r];
    }
    __syncthreads();

    int tx = tid & 15;
    int ty = tid >> 4;
    float acc[4][4];
#pragma unroll
    for (int i = 0; i < 4; i++)
#pragma unroll
        for (int j = 0; j < 4; j++) acc[i][j] = 0.f;

#pragma unroll 4
    for (int r = 0; r < 64; r++) {
        float a0 = wsl[r * 64 + ty * 4 + 0];
        float a1 = wsl[r * 64 + ty * 4 + 1];
        float a2 = wsl[r * 64 + ty * 4 + 2];
        float a3 = wsl[r * 64 + ty * 4 + 3];
        float4 bv = *(const float4*)&aos[r * 64 + tx * 4];
        acc[0][0] += a0 * bv.x; acc[0][1] += a0 * bv.y; acc[0][2] += a0 * bv.z; acc[0][3] += a0 * bv.w;
        acc[1][0] += a1 * bv.x; acc[1][1] += a1 * bv.y; acc[1][2] += a1 * bv.z; acc[1][3] += a1 * bv.w;
        acc[2][0] += a2 * bv.x; acc[2][1] += a2 * bv.y; acc[2][2] += a2 * bv.z; acc[2][3] += a2 * bv.w;
        acc[3][0] += a3 * bv.x; acc[3][1] += a3 * bv.y; acc[3][2] += a3 * bv.z; acc[3][3] += a3 * bv.w;
    }

    float g = gamma[0];
#pragma unroll
    for (int i = 0; i < 4; i++) {
        int c = cT * 64 + ty * 4 + i;
        size_t base = ((size_t)b * CC + c) * NTOK + nb + tx * 4;
        float4 xv = *(const float4*)(x + base);
        float4 r;
        float z0 = g * acc[i][0] + xv.x;
        float z1 = g * acc[i][1] + xv.y;
        float z2 = g * acc[i][2] + xv.z;
        float z3 = g * acc[i][3] + xv.w;
        r.x = 1.f / (1.f + __expf(-z0));
        r.y = 1.f / (1.f + __expf(-z1));
        r.z = 1.f / (1.f + __expf(-z2));
        r.w = 1.f / (1.f + __expf(-z3));
        *(float4*)(out + base) = r;
    }
}

// ---------------------------------------------------------------------------
// Launch
// ---------------------------------------------------------------------------
extern "C" void kernel_launch(void* const* d_in, const int* in_sizes, int n_in,
                              void* d_out, int out_size) {
    const float* x       = (const float*)d_in[0];
    const float* norm_w  = (const float*)d_in[1];
    const float* norm_b  = (const float*)d_in[2];
    const float* qkv_w   = (const float*)d_in[3];
    const float* out_w   = (const float*)d_in[4];
    const float* conv1_w = (const float*)d_in[5];
    const float* conv1_b = (const float*)d_in[6];
    const float* conv2_w = (const float*)d_in[7];
    const float* conv2_b = (const float*)d_in[8];
    const float* gamma   = (const float*)d_in[9];
    float* out = (float*)d_out;
    (void)in_sizes; (void)n_in; (void)out_size;

    const int proj_smem = (64 * 256 + 64 * 128) * sizeof(float);   // 98304
    cudaFuncSetAttribute(proj_kernel, cudaFuncAttributeMaxDynamicSharedMemorySize, proj_smem);

    prep_kernel<<<OPROJ, 256>>>(qkv_w, conv1_w, norm_w, norm_b);
    stats_kernel<<<BN / 128, 128>>>(x);
    proj_kernel<<<dim3(BN / 128, 5), 256, proj_smem>>>(x, conv1_b, conv2_w);
    attn_kernel<<<dim3(NTOK / 256, BB * NH, NSPLIT), 256>>>(0);
    combine_kernel<<<BB * NH * NTOK / 256, 256>>>(conv2_b);
    out_kernel<<<dim3(BN / 64, CC / 64), 256>>>(x, out_w, gamma, out);
}

// round 3
// speedup vs baseline: 2.8526x; 2.0343x over previous
#include <cuda_runtime.h>
#include <cuda_bf16.h>
#include <cstdint>

// ---------------------------------------------------------------------------
// Problem constants
// ---------------------------------------------------------------------------
#define CC     256          // channels
#define NTOK   4096         // H*W
#define BB     2            // batch
#define BN     (BB*NTOK)    // 8192 tokens
#define RED    64
#define NH     4
#define HD     16
#define QKV_O  192          // 3*RED
#define OPROJ  320          // 192 qkv + 128 conv1
#define LN_EPS 1e-5f
#define ATT_SCALE 0.25f     // HD^-0.5
#define LOG2E  1.4426950408889634f
#define QSCALE (ATT_SCALE * LOG2E)

// ---------------------------------------------------------------------------
// Device scratch (no allocations allowed)
// ---------------------------------------------------------------------------
__device__ float g_wcomb[OPROJ * CC];
__device__ float g_Sq[QKV_O];
__device__ float g_Sb[QKV_O];
__device__ float g_mu[BN];
__device__ float g_rsig[BN];
__device__ float g_q[BB * NH * NTOK * HD];
__device__ float g_k[BB * NH * NTOK * HD];
__device__ float g_v[BB * NH * NTOK * HD];
__device__ float g_dynpart[2 * BN];
__device__ float g_ao[BN * RED];

// ---------------------------------------------------------------------------
// small asm helpers
// ---------------------------------------------------------------------------
__device__ __forceinline__ uint32_t f2tf32(float x) {
    uint32_t r; asm("cvt.rna.tf32.f32 %0, %1;" : "=r"(r) : "f"(x)); return r;
}
__device__ __forceinline__ uint32_t pbf16x2(float lo, float hi) {
    uint32_t r; asm("cvt.rn.bf16x2.f32 %0, %1, %2;" : "=r"(r) : "f"(hi), "f"(lo)); return r;
}
__device__ __forceinline__ float ex2f(float x) {
    float r; asm("ex2.approx.f32 %0, %1;" : "=f"(r) : "f"(x)); return r;
}

// QK: m16n8k8 tf32, first k-step writes (C input = 0), second accumulates
__device__ __forceinline__ void mma_tf32_z(float* d, const uint32_t* a, uint32_t b0, uint32_t b1) {
    asm volatile(
        "mma.sync.aligned.m16n8k8.row.col.f32.tf32.tf32.f32 "
        "{%0,%1,%2,%3}, {%4,%5,%6,%7}, {%8,%9}, {%10,%11,%12,%13};"
        : "=f"(d[0]), "=f"(d[1]), "=f"(d[2]), "=f"(d[3])
        : "r"(a[0]), "r"(a[1]), "r"(a[2]), "r"(a[3]), "r"(b0), "r"(b1),
          "f"(0.f), "f"(0.f), "f"(0.f), "f"(0.f));
}
__device__ __forceinline__ void mma_tf32(float* c, const uint32_t* a, uint32_t b0, uint32_t b1) {
    asm volatile(
        "mma.sync.aligned.m16n8k8.row.col.f32.tf32.tf32.f32 "
        "{%0,%1,%2,%3}, {%4,%5,%6,%7}, {%8,%9}, {%0,%1,%2,%3};"
        : "+f"(c[0]), "+f"(c[1]), "+f"(c[2]), "+f"(c[3])
        : "r"(a[0]), "r"(a[1]), "r"(a[2]), "r"(a[3]), "r"(b0), "r"(b1));
}
// PV: m16n8k16 bf16 accumulate
__device__ __forceinline__ void mma_bf16(float* c, uint32_t a0, uint32_t a1, uint32_t a2, uint32_t a3,
                                         uint32_t b0, uint32_t b1) {
    asm volatile(
        "mma.sync.aligned.m16n8k16.row.col.f32.bf16.bf16.f32 "
        "{%0,%1,%2,%3}, {%4,%5,%6,%7}, {%8,%9}, {%0,%1,%2,%3};"
        : "+f"(c[0]), "+f"(c[1]), "+f"(c[2]), "+f"(c[3])
        : "r"(a0), "r"(a1), "r"(a2), "r"(a3), "r"(b0), "r"(b1));
}

// ---------------------------------------------------------------------------
// Kernel 0: fold norm_w into qkv weights, build combined [320,256] weight.
// ---------------------------------------------------------------------------
__global__ __launch_bounds__(256) void prep_kernel(const float* __restrict__ qkv_w,
                                                   const float* __restrict__ conv1_w,
                                                   const float* __restrict__ norm_w,
                                                   const float* __restrict__ norm_b) {
    int o = blockIdx.x;
    int c = threadIdx.x;
    __shared__ float r1[256];
    __shared__ float r2[256];
    float wc;
    if (o < QKV_O) {
        float qw = qkv_w[o * CC + c];
        wc = qw * norm_w[c];
        r1[c] = wc;
        r2[c] = qw * norm_b[c];
    } else {
        wc = conv1_w[(o - QKV_O) * CC + c];
        r1[c] = 0.f;
        r2[c] = 0.f;
    }
    g_wcomb[o * CC + c] = wc;
    __syncthreads();
    for (int s = 128; s > 0; s >>= 1) {
        if (c < s) { r1[c] += r1[c + s]; r2[c] += r2[c + s]; }
        __syncthreads();
    }
    if (c == 0 && o < QKV_O) { g_Sq[o] = r1[0]; g_Sb[o] = r2[0]; }
}

// ---------------------------------------------------------------------------
// Kernel 1: per-token LayerNorm stats.
// ---------------------------------------------------------------------------
__global__ __launch_bounds__(128) void stats_kernel(const float* __restrict__ x) {
    int tok = blockIdx.x * 128 + threadIdx.x;
    int b = tok >> 12;
    int n = tok & (NTOK - 1);
    const float* xp = x + (size_t)b * CC * NTOK + n;
    float s = 0.f, ss = 0.f;
#pragma unroll 8
    for (int c = 0; c < CC; c++) {
        float v = xp[(size_t)c * NTOK];
        s += v;
        ss += v * v;
    }
    float mu = s * (1.f / CC);
    float var = ss * (1.f / CC) - mu * mu;
    g_mu[tok] = mu;
    g_rsig[tok] = rsqrtf(var + LN_EPS);
}

// ---------------------------------------------------------------------------
// Kernel 2: projection GEMM (qkv + conv branch), unchanged from R2.
// ---------------------------------------------------------------------------
__global__ __launch_bounds__(256) void proj_kernel(const float* __restrict__ x,
                                                   const float* __restrict__ conv1_b,
                                                   const float* __restrict__ conv2_w) {
    extern __shared__ float sm[];
    float* ws = sm;               // 64 x 256
    float* xs = sm + 64 * 256;    // 64 x 128

    int tid = threadIdx.x;
    int oT = blockIdx.y;
    int tokb = blockIdx.x * 128;
    int b = tokb >> 12;
    int nb = tokb & (NTOK - 1);

    for (int i = tid; i < 64 * 256; i += 256)
        ws[i] = g_wcomb[oT * 64 * 256 + i];

    int tx = tid & 15;
    int ty = tid >> 4;

    float acc[4][8];
#pragma unroll
    for (int i = 0; i < 4; i++)
#pragma unroll
        for (int j = 0; j < 8; j++) acc[i][j] = 0.f;

    for (int kc = 0; kc < 4; kc++) {
        __syncthreads();
        for (int i = tid; i < 64 * 128; i += 256) {
            int kk = i >> 7;
            int t = i & 127;
            xs[i] = x[((size_t)b * CC + kc * 64 + kk) * NTOK + nb + t];
        }
        __syncthreads();
#pragma unroll 2
        for (int kk = 0; kk < 64; kk++) {
            int c = kc * 64 + kk;
            float a0 = ws[(ty * 4 + 0) * 256 + c];
            float a1 = ws[(ty * 4 + 1) * 256 + c];
            float a2 = ws[(ty * 4 + 2) * 256 + c];
            float a3 = ws[(ty * 4 + 3) * 256 + c];
            const float* xr = &xs[kk * 128 + tx * 8];
            float4 b0 = *(const float4*)xr;
            float4 b1 = *(const float4*)(xr + 4);
            acc[0][0] += a0 * b0.x; acc[0][1] += a0 * b0.y; acc[0][2] += a0 * b0.z; acc[0][3] += a0 * b0.w;
            acc[0][4] += a0 * b1.x; acc[0][5] += a0 * b1.y; acc[0][6] += a0 * b1.z; acc[0][7] += a0 * b1.w;
            acc[1][0] += a1 * b0.x; acc[1][1] += a1 * b0.y; acc[1][2] += a1 * b0.z; acc[1][3] += a1 * b0.w;
            acc[1][4] += a1 * b1.x; acc[1][5] += a1 * b1.y; acc[1][6] += a1 * b1.z; acc[1][7] += a1 * b1.w;
            acc[2][0] += a2 * b0.x; acc[2][1] += a2 * b0.y; acc[2][2] += a2 * b0.z; acc[2][3] += a2 * b0.w;
            acc[2][4] += a2 * b1.x; acc[2][5] += a2 * b1.y; acc[2][6] += a2 * b1.z; acc[2][7] += a2 * b1.w;
            acc[3][0] += a3 * b0.x; acc[3][1] += a3 * b0.y; acc[3][2] += a3 * b0.z; acc[3][3] += a3 * b0.w;
            acc[3][4] += a3 * b1.x; acc[3][5] += a3 * b1.y; acc[3][6] += a3 * b1.z; acc[3][7] += a3 * b1.w;
        }
    }

    if (oT < 3) {
        float muv[8], rsv[8];
#pragma unroll
        for (int j = 0; j < 8; j++) {
            int tok = tokb + tx * 8 + j;
            muv[j] = g_mu[tok];
            rsv[j] = g_rsig[tok];
        }
#pragma unroll
        for (int i = 0; i < 4; i++) {
            int o = oT * 64 + ty * 4 + i;
            float sq = g_Sq[o];
            float sb = g_Sb[o];
            int which = o >> 6;
            int oo = o & 63;
            int h = oo >> 4;
            int d = oo & 15;
            float* dst = (which == 0) ? g_q : (which == 1) ? g_k : g_v;
#pragma unroll
            for (int j = 0; j < 8; j++) {
                int n = nb + tx * 8 + j;
                float val = rsv[j] * (acc[i][j] - muv[j] * sq) + sb;
                dst[(((size_t)b * NH + h) * NTOK + n) * HD + d] = val;
            }
        }
    } else {
        float part[8];
#pragma unroll
        for (int j = 0; j < 8; j++) part[j] = 0.f;
#pragma unroll
        for (int i = 0; i < 4; i++) {
            int jc = oT * 64 + ty * 4 + i - QKV_O;
            float cb = conv1_b[jc];
            float cw = conv2_w[jc];
#pragma unroll
            for (int j = 0; j < 8; j++) {
                float d1 = fmaxf(acc[i][j] + cb, 0.f);
                part[j] += cw * d1;
            }
        }
        __syncthreads();
        float* red = xs;
#pragma unroll
        for (int j = 0; j < 8; j++) red[ty * 128 + tx * 8 + j] = part[j];
        __syncthreads();
        if (tid < 128) {
            float s = 0.f;
#pragma unroll
            for (int yy = 0; yy < 16; yy++) s += red[yy * 128 + tid];
            g_dynpart[(oT - 3) * BN + tokb + tid] = s;
        }
    }
}

// ---------------------------------------------------------------------------
// Kernel 3: flash attention on mma.sync tensor cores.
// CTA: 256 threads = 8 warps; warp w owns 16 queries; CTA owns 128 queries.
// Key tiles of 64. QK^T in tf32 (m16n8k8), P·V in bf16 (m16n8k16).
// Epilogue folds dyn/l and writes g_ao. Grid: (NTOK/128, BB*NH).
// ---------------------------------------------------------------------------
#define KT 64               // keys per tile
#define QT 128              // queries per CTA
#define KSTRIDE 20          // padded f32/tf32 row stride (conflict-free frags)
#define VSTRIDE 36          // padded bf16x2-word row stride for V^T

__global__ __launch_bounds__(256) void attn_kernel(const float* __restrict__ conv2_b) {
    __shared__ uint32_t qs[QT * KSTRIDE];    // Q tile, tf32 bits, pre-scaled
    __shared__ uint32_t ks[KT * KSTRIDE];    // K tile, tf32 bits
    __shared__ uint32_t vs[HD * VSTRIDE];    // V^T tile, bf16x2 (key pairs)

    int tid = threadIdx.x;
    int w = tid >> 5;
    int lane = tid & 31;
    int lq = lane >> 2;     // fragment row (quad id)
    int lc = lane & 3;      // fragment col group
    int bh = blockIdx.y;
    int qbase = blockIdx.x * QT;

    // ---- stage Q (once), scaled by QSCALE, rounded to tf32 ----
    {
        const float4* qg = (const float4*)(g_q + ((size_t)bh * NTOK + qbase) * HD);
#pragma unroll
        for (int it = 0; it < 2; it++) {
            int f = tid + it * 256;                 // 512 float4 total
            int row = f >> 2, db = (f & 3) * 4;
            float4 v = qg[f];
            uint32_t* d = &qs[row * KSTRIDE + db];
            d[0] = f2tf32(v.x * QSCALE);
            d[1] = f2tf32(v.y * QSCALE);
            d[2] = f2tf32(v.z * QSCALE);
            d[3] = f2tf32(v.w * QSCALE);
        }
    }
    __syncthreads();

    // ---- load Q fragments (per warp, 16 rows) ----
    uint32_t aq[2][4];
    {
        int r0 = w * 16 + lq;
#pragma unroll
        for (int kstep = 0; kstep < 2; kstep++) {
            int d0 = 8 * kstep + lc;
            aq[kstep][0] = qs[r0 * KSTRIDE + d0];
            aq[kstep][1] = qs[(r0 + 8) * KSTRIDE + d0];
            aq[kstep][2] = qs[r0 * KSTRIDE + d0 + 4];
            aq[kstep][3] = qs[(r0 + 8) * KSTRIDE + d0 + 4];
        }
    }

    float o[2][4];
#pragma unroll
    for (int i = 0; i < 2; i++)
#pragma unroll
        for (int j = 0; j < 4; j++) o[i][j] = 0.f;
    float m0 = -1e30f, m1 = -1e30f;
    float l0 = 0.f, l1 = 0.f;

    const float* kg_base = g_k + (size_t)bh * NTOK * HD;
    const float* vg_base = g_v + (size_t)bh * NTOK * HD;

    for (int kt = 0; kt < NTOK / KT; kt++) {
        __syncthreads();
        // ---- stage K tile (tf32) ----
        {
            const float4* kg = (const float4*)(kg_base + (size_t)kt * KT * HD);
            int f = tid;                            // 256 float4
            int row = f >> 2, db = (f & 3) * 4;
            float4 v = kg[f];
            uint32_t* d = &ks[row * KSTRIDE + db];
            d[0] = f2tf32(v.x);
            d[1] = f2tf32(v.y);
            d[2] = f2tf32(v.z);
            d[3] = f2tf32(v.w);
        }
        // ---- stage V^T tile (bf16x2, key pairs along rows of d) ----
        {
            const float* vg = vg_base + (size_t)kt * KT * HD;
#pragma unroll
            for (int it = 0; it < 2; it++) {
                int i = tid + it * 256;             // 512 pairs
                int d = i & 15, kp = i >> 4;        // kp 0..31
                float v0 = vg[(2 * kp) * HD + d];
                float v1 = vg[(2 * kp + 1) * HD + d];
                vs[d * VSTRIDE + kp] = pbf16x2(v0, v1);
            }
        }
        __syncthreads();

        // ---- S = Q K^T  (16 q-rows x 64 keys per warp) ----
        float c[8][4];
#pragma unroll
        for (int nb = 0; nb < 8; nb++) {
            const uint32_t* kr = &ks[(nb * 8 + lq) * KSTRIDE + lc];
            uint32_t b0a = kr[0];
            uint32_t b1a = kr[4];
            uint32_t b0b = kr[8];
            uint32_t b1b = kr[12];
            mma_tf32_z(c[nb], aq[0], b0a, b1a);
            mma_tf32(c[nb], aq[1], b0b, b1b);
        }

        // ---- online softmax (scores already in log2 domain) ----
        float rm0 = c[0][0], rm1 = c[0][2];
#pragma unroll
        for (int nb = 0; nb < 8; nb++) {
            rm0 = fmaxf(rm0, fmaxf(c[nb][0], c[nb][1]));
            rm1 = fmaxf(rm1, fmaxf(c[nb][2], c[nb][3]));
        }
        rm0 = fmaxf(rm0, __shfl_xor_sync(0xffffffffu, rm0, 1));
        rm0 = fmaxf(rm0, __shfl_xor_sync(0xffffffffu, rm0, 2));
        rm1 = fmaxf(rm1, __shfl_xor_sync(0xffffffffu, rm1, 1));
        rm1 = fmaxf(rm1, __shfl_xor_sync(0xffffffffu, rm1, 2));

        float mn0 = fmaxf(m0, rm0);
        float mn1 = fmaxf(m1, rm1);
        float cor0 = ex2f(m0 - mn0);
        float cor1 = ex2f(m1 - mn1);
        m0 = mn0; m1 = mn1;

        float s0 = 0.f, s1 = 0.f;
#pragma unroll
        for (int nb = 0; nb < 8; nb++) {
            c[nb][0] = ex2f(c[nb][0] - mn0);
            c[nb][1] = ex2f(c[nb][1] - mn0);
            c[nb][2] = ex2f(c[nb][2] - mn1);
            c[nb][3] = ex2f(c[nb][3] - mn1);
            s0 += c[nb][0] + c[nb][1];
            s1 += c[nb][2] + c[nb][3];
        }
        s0 += __shfl_xor_sync(0xffffffffu, s0, 1);
        s0 += __shfl_xor_sync(0xffffffffu, s0, 2);
        s1 += __shfl_xor_sync(0xffffffffu, s1, 1);
        s1 += __shfl_xor_sync(0xffffffffu, s1, 2);
        l0 = l0 * cor0 + s0;
        l1 = l1 * cor1 + s1;

#pragma unroll
        for (int nd = 0; nd < 2; nd++) {
            o[nd][0] *= cor0; o[nd][1] *= cor0;
            o[nd][2] *= cor1; o[nd][3] *= cor1;
        }

        // ---- O += P V  (bf16 MMAs) ----
#pragma unroll
        for (int kk = 0; kk < 4; kk++) {
            uint32_t pa0 = pbf16x2(c[2 * kk][0], c[2 * kk][1]);
            uint32_t pa1 = pbf16x2(c[2 * kk][2], c[2 * kk][3]);
            uint32_t pa2 = pbf16x2(c[2 * kk + 1][0], c[2 * kk + 1][1]);
            uint32_t pa3 = pbf16x2(c[2 * kk + 1][2], c[2 * kk + 1][3]);
#pragma unroll
            for (int nd = 0; nd < 2; nd++) {
                int d = 8 * nd + lq;
                uint32_t b0 = vs[d * VSTRIDE + lc + 8 * kk];
                uint32_t b1 = vs[d * VSTRIDE + lc + 8 * kk + 4];
                mma_bf16(o[nd], pa0, pa1, pa2, pa3, b0, b1);
            }
        }
    }

    // ---- epilogue: fold dyn/l, write g_ao ----
    int b = bh >> 2;
    int h = bh & 3;
    int n0 = qbase + w * 16 + lq;
    int n1 = n0 + 8;
    int tok0 = b * NTOK + n0;
    int tok1 = b * NTOK + n1;
    float c2b = conv2_b[0];
    float sc0 = (g_dynpart[tok0] + g_dynpart[BN + tok0] + c2b) / l0;
    float sc1 = (g_dynpart[tok1] + g_dynpart[BN + tok1] + c2b) / l1;

    float* dst0 = g_ao + (size_t)tok0 * RED + h * HD;
    float* dst1 = g_ao + (size_t)tok1 * RED + h * HD;
#pragma unroll
    for (int nd = 0; nd < 2; nd++) {
        float2 w0 = make_float2(o[nd][0] * sc0, o[nd][1] * sc0);
        float2 w1 = make_float2(o[nd][2] * sc1, o[nd][3] * sc1);
        *(float2*)(dst0 + 8 * nd + 2 * lc) = w0;
        *(float2*)(dst1 + 8 * nd + 2 * lc) = w1;
    }
}

// ---------------------------------------------------------------------------
// Kernel 4: out-projection + residual + sigmoid (unchanged).
// ---------------------------------------------------------------------------
__global__ __launch_bounds__(256) void out_kernel(const float* __restrict__ x,
                                                  const float* __restrict__ out_w,
                                                  const float* __restrict__ gamma,
                                                  float* __restrict__ out) {
    __shared__ float wsl[64 * 64];
    __shared__ float aos[64 * 64];
    int tid = threadIdx.x;
    int tokb = blockIdx.x * 64;
    int cT = blockIdx.y;
    int b = tokb >> 12;
    int nb = tokb & (NTOK - 1);

    for (int i = tid; i < 64 * 64; i += 256) {
        int t = i >> 6;
        int r = i & 63;
        aos[r * 64 + t] = g_ao[(size_t)(tokb + t) * RED + r];
        wsl[r * 64 + t] = out_w[(size_t)(cT * 64 + t) * RED + r];
    }
    __syncthreads();

    int tx = tid & 15;
    int ty = tid >> 4;
    float acc[4][4];
#pragma unroll
    for (int i = 0; i < 4; i++)
#pragma unroll
        for (int j = 0; j < 4; j++) acc[i][j] = 0.f;

#pragma unroll 4
    for (int r = 0; r < 64; r++) {
        float a0 = wsl[r * 64 + ty * 4 + 0];
        float a1 = wsl[r * 64 + ty * 4 + 1];
        float a2 = wsl[r * 64 + ty * 4 + 2];
        float a3 = wsl[r * 64 + ty * 4 + 3];
        float4 bv = *(const float4*)&aos[r * 64 + tx * 4];
        acc[0][0] += a0 * bv.x; acc[0][1] += a0 * bv.y; acc[0][2] += a0 * bv.z; acc[0][3] += a0 * bv.w;
        acc[1][0] += a1 * bv.x; acc[1][1] += a1 * bv.y; acc[1][2] += a1 * bv.z; acc[1][3] += a1 * bv.w;
        acc[2][0] += a2 * bv.x; acc[2][1] += a2 * bv.y; acc[2][2] += a2 * bv.z; acc[2][3] += a2 * bv.w;
        acc[3][0] += a3 * bv.x; acc[3][1] += a3 * bv.y; acc[3][2] += a3 * bv.z; acc[3][3] += a3 * bv.w;
    }

    float g = gamma[0];
#pragma unroll
    for (int i = 0; i < 4; i++) {
        int c = cT * 64 + ty * 4 + i;
        size_t base = ((size_t)b * CC + c) * NTOK + nb + tx * 4;
        float4 xv = *(const float4*)(x + base);
        float4 r;
        float z0 = g * acc[i][0] + xv.x;
        float z1 = g * acc[i][1] + xv.y;
        float z2 = g * acc[i][2] + xv.z;
        float z3 = g * acc[i][3] + xv.w;
        r.x = 1.f / (1.f + __expf(-z0));
        r.y = 1.f / (1.f + __expf(-z1));
        r.z = 1.f / (1.f + __expf(-z2));
        r.w = 1.f / (1.f + __expf(-z3));
        *(float4*)(out + base) = r;
    }
}

// ---------------------------------------------------------------------------
// Launch
// ---------------------------------------------------------------------------
extern "C" void kernel_launch(void* const* d_in, const int* in_sizes, int n_in,
                              void* d_out, int out_size) {
    const float* x       = (const float*)d_in[0];
    const float* norm_w  = (const float*)d_in[1];
    const float* norm_b  = (const float*)d_in[2];
    const float* qkv_w   = (const float*)d_in[3];
    const float* out_w   = (const float*)d_in[4];
    const float* conv1_w = (const float*)d_in[5];
    const float* conv1_b = (const float*)d_in[6];
    const float* conv2_w = (const float*)d_in[7];
    const float* conv2_b = (const float*)d_in[8];
    const float* gamma   = (const float*)d_in[9];
    float* out = (float*)d_out;
    (void)in_sizes; (void)n_in; (void)out_size;

    const int proj_smem = (64 * 256 + 64 * 128) * sizeof(float);
    cudaFuncSetAttribute(proj_kernel, cudaFuncAttributeMaxDynamicSharedMemorySize, proj_smem);

    prep_kernel<<<OPROJ, 256>>>(qkv_w, conv1_w, norm_w, norm_b);
    stats_kernel<<<BN / 128, 128>>>(x);
    proj_kernel<<<dim3(BN / 128, 5), 256, proj_smem>>>(x, conv1_b, conv2_w);
    attn_kernel<<<dim3(NTOK / QT, BB * NH), 256>>>(conv2_b);
    out_kernel<<<dim3(BN / 64, CC / 64), 256>>>(x, out_w, gamma, out);
}